// round 5
// baseline (speedup 1.0000x reference)
#include <cuda_runtime.h>
#include <cuda_bf16.h>
#include <cstdint>

#define BATCH 2
#define NSEQ  2048
#define CH    768
#define NH    12
#define DH    64
#define WIN   7
#define C3    (3*CH)
#define MTOT  (BATCH*NSEQ)   // 4096
#define KDIM  CH             // 768
#define BK    32
#define NCHUNK (KDIM/BK)     // 24
#define NSTAGE 4

// ---------------- scratch (allocation-free) ----------------
__device__ float         g_qkv[(size_t)MTOT*C3];
__device__ __nv_bfloat16 g_xhi[(size_t)MTOT*CH], g_xlo[(size_t)MTOT*CH];
__device__ __nv_bfloat16 g_qhi[(size_t)C3*CH],  g_qlo[(size_t)C3*CH];
__device__ __nv_bfloat16 g_phi[(size_t)CH*CH],  g_plo[(size_t)CH*CH];
__device__ __nv_bfloat16 g_ahi[(size_t)MTOT*CH], g_alo[(size_t)MTOT*CH];

// ---------------- helpers ----------------
__device__ __forceinline__ uint32_t smem_u32(const void* p) {
    uint32_t a;
    asm("{ .reg .u64 t; cvta.to.shared.u64 t, %1; cvt.u32.u64 %0, t; }" : "=r"(a) : "l"(p));
    return a;
}
__device__ __forceinline__ void cp16(uint32_t dst, const void* src) {
    asm volatile("cp.async.cg.shared.global [%0], [%1], 16;" :: "r"(dst), "l"(src) : "memory");
}
#define CP_COMMIT() asm volatile("cp.async.commit_group;" ::: "memory")
#define CP_WAIT2()  asm volatile("cp.async.wait_group 2;" ::: "memory")

#define LDSM_X4(r0, r1, r2, r3, addr)                                            \
    asm volatile("ldmatrix.sync.aligned.m8n8.x4.shared.b16 {%0,%1,%2,%3}, [%4];" \
                 : "=r"(r0), "=r"(r1), "=r"(r2), "=r"(r3) : "r"(addr))

#define MMA_BF16(acc, a, b0, b1)                                              \
    asm("mma.sync.aligned.m16n8k16.row.col.f32.bf16.bf16.f32 "                \
        "{%0,%1,%2,%3},{%4,%5,%6,%7},{%8,%9},{%0,%1,%2,%3};"                  \
        : "+f"((acc)[0]), "+f"((acc)[1]), "+f"((acc)[2]), "+f"((acc)[3])      \
        : "r"((a)[0]), "r"((a)[1]), "r"((a)[2]), "r"((a)[3]),                 \
          "r"(b0), "r"(b1))

__device__ __forceinline__ uint32_t swz(int row, int colb) {
    return (uint32_t)(row * 64 + (colb ^ ((row & 6) << 3)));
}

// ---------------- fp32 -> bf16 hi/lo split ----------------
__global__ void __launch_bounds__(256)
split_bf16(const float* __restrict__ in, __nv_bfloat16* __restrict__ hi,
           __nv_bfloat16* __restrict__ lo, int n4)
{
    int idx = blockIdx.x * blockDim.x + threadIdx.x;
    if (idx >= n4) return;
    float4 v = ((const float4*)in)[idx];
    __nv_bfloat16 h0 = __float2bfloat16(v.x), h1 = __float2bfloat16(v.y);
    __nv_bfloat16 h2 = __float2bfloat16(v.z), h3 = __float2bfloat16(v.w);
    __nv_bfloat16 l0 = __float2bfloat16(v.x - __bfloat162float(h0));
    __nv_bfloat16 l1 = __float2bfloat16(v.y - __bfloat162float(h1));
    __nv_bfloat16 l2 = __float2bfloat16(v.z - __bfloat162float(h2));
    __nv_bfloat16 l3 = __float2bfloat16(v.w - __bfloat162float(h3));
    __nv_bfloat162* hp = (__nv_bfloat162*)(hi + 4 * (size_t)idx);
    __nv_bfloat162* lp = (__nv_bfloat162*)(lo + 4 * (size_t)idx);
    hp[0] = __nv_bfloat162(h0, h1); hp[1] = __nv_bfloat162(h2, h3);
    lp[0] = __nv_bfloat162(l0, l1); lp[1] = __nv_bfloat162(l2, l3);
}

// ---------------- HMMA GEMM: 4-stage cp.async ring, 1 sync/chunk ----------------
// Stage layout: [Ahi BM*64][Alo BM*64][Whi 8192][Wlo 8192]
template<int BM_, int NT, int MINCTA>
__global__ void __launch_bounds__(NT, MINCTA)
gemm_mma(const __nv_bfloat16* __restrict__ Ahi, const __nv_bfloat16* __restrict__ Alo,
         const __nv_bfloat16* __restrict__ Whi, const __nv_bfloat16* __restrict__ Wlo,
         const float* __restrict__ bias, float* __restrict__ C, int N)
{
    constexpr int WARPS_M = BM_ / 32;
    constexpr int ATILE   = BM_ * 64;
    constexpr int STAGEB  = 2 * ATILE + 16384;

    extern __shared__ char smem[];
    const uint32_t sb = smem_u32(smem);
    const int tid = threadIdx.x, wid = tid >> 5, lane = tid & 31;
    const int m0 = blockIdx.y * BM_, n0 = blockIdx.x * 128;
    const int wm = (wid % WARPS_M) * 32;
    const int wn = (wid / WARPS_M) * 32;

    const char* pAh = (const char*)Ahi;
    const char* pAl = (const char*)Alo;
    const char* pWh = (const char*)Whi;
    const char* pWl = (const char*)Wlo;

    float acc[2][4][4];
    #pragma unroll
    for (int i = 0; i < 2; i++)
        #pragma unroll
        for (int j = 0; j < 4; j++)
            #pragma unroll
            for (int t = 0; t < 4; t++) acc[i][j][t] = 0.f;

    auto fill_stage = [&](uint32_t stb, int k0) {
        #pragma unroll
        for (int s = tid; s < BM_ * 4; s += NT) {
            int row = s >> 2, ks = s & 3;
            uint32_t so = swz(row, ks * 16);
            size_t ga = ((size_t)(m0 + row) * KDIM + k0 + ks * 8) * 2;
            cp16(stb + so,         pAh + ga);
            cp16(stb + ATILE + so, pAl + ga);
        }
        #pragma unroll
        for (int s = tid; s < 512; s += NT) {
            int row = s >> 2, ks = s & 3;
            uint32_t so = swz(row, ks * 16);
            size_t gw = ((size_t)(n0 + row) * KDIM + k0 + ks * 8) * 2;
            cp16(stb + 2 * ATILE + so,        pWh + gw);
            cp16(stb + 2 * ATILE + 8192 + so, pWl + gw);
        }
    };

    // prologue: 3 chunks into stages 0..2
    #pragma unroll
    for (int c = 0; c < 3; c++) {
        fill_stage(sb + c * STAGEB, c * BK);
        CP_COMMIT();
    }

    const int r = lane & 15, cg = lane >> 4;

    for (int c = 0; c < NCHUNK; c++) {
        const uint32_t stb = sb + (c % NSTAGE) * STAGEB;
        CP_WAIT2();
        __syncthreads();          // single barrier per chunk

        uint32_t ah[2][4], al[2][4], bh[2][4], bl[2][4];

        // ---- LDSM k-step 0 ----
        #pragma unroll
        for (int mt = 0; mt < 2; mt++) {
            uint32_t ad = stb + swz(wm + mt * 16 + r, cg * 16);
            LDSM_X4(ah[mt][0], ah[mt][1], ah[mt][2], ah[mt][3], ad);
            LDSM_X4(al[mt][0], al[mt][1], al[mt][2], al[mt][3], ad + ATILE);
        }
        #pragma unroll
        for (int bt = 0; bt < 2; bt++) {
            uint32_t ad = stb + 2 * ATILE + swz(wn + bt * 16 + r, cg * 16);
            LDSM_X4(bh[bt][0], bh[bt][1], bh[bt][2], bh[bt][3], ad);
            LDSM_X4(bl[bt][0], bl[bt][1], bl[bt][2], bl[bt][3], ad + 8192);
        }

        // ---- refill stage consumed at chunk c-1 with chunk c+3 (covers LDSM latency) ----
        if (c + 3 < NCHUNK)
            fill_stage(sb + ((c + 3) % NSTAGE) * STAGEB, (c + 3) * BK);
        CP_COMMIT();

        // ---- MMA k-step 0 (products outer -> independent acc chains) ----
        #pragma unroll
        for (int nt = 0; nt < 4; nt++) {
            uint32_t b0 = bh[nt >> 1][nt & 1], b1 = bh[nt >> 1][2 + (nt & 1)];
            MMA_BF16(acc[0][nt], ah[0], b0, b1);
            MMA_BF16(acc[1][nt], ah[1], b0, b1);
        }
        #pragma unroll
        for (int nt = 0; nt < 4; nt++) {
            uint32_t b0 = bl[nt >> 1][nt & 1], b1 = bl[nt >> 1][2 + (nt & 1)];
            MMA_BF16(acc[0][nt], ah[0], b0, b1);
            MMA_BF16(acc[1][nt], ah[1], b0, b1);
        }
        #pragma unroll
        for (int nt = 0; nt < 4; nt++) {
            uint32_t b0 = bh[nt >> 1][nt & 1], b1 = bh[nt >> 1][2 + (nt & 1)];
            MMA_BF16(acc[0][nt], al[0], b0, b1);
            MMA_BF16(acc[1][nt], al[1], b0, b1);
        }

        // ---- LDSM k-step 1 ----
        #pragma unroll
        for (int mt = 0; mt < 2; mt++) {
            uint32_t ad = stb + swz(wm + mt * 16 + r, 32 + cg * 16);
            LDSM_X4(ah[mt][0], ah[mt][1], ah[mt][2], ah[mt][3], ad);
            LDSM_X4(al[mt][0], al[mt][1], al[mt][2], al[mt][3], ad + ATILE);
        }
        #pragma unroll
        for (int bt = 0; bt < 2; bt++) {
            uint32_t ad = stb + 2 * ATILE + swz(wn + bt * 16 + r, 32 + cg * 16);
            LDSM_X4(bh[bt][0], bh[bt][1], bh[bt][2], bh[bt][3], ad);
            LDSM_X4(bl[bt][0], bl[bt][1], bl[bt][2], bl[bt][3], ad + 8192);
        }

        // ---- MMA k-step 1 ----
        #pragma unroll
        for (int nt = 0; nt < 4; nt++) {
            uint32_t b0 = bh[nt >> 1][nt & 1], b1 = bh[nt >> 1][2 + (nt & 1)];
            MMA_BF16(acc[0][nt], ah[0], b0, b1);
            MMA_BF16(acc[1][nt], ah[1], b0, b1);
        }
        #pragma unroll
        for (int nt = 0; nt < 4; nt++) {
            uint32_t b0 = bl[nt >> 1][nt & 1], b1 = bl[nt >> 1][2 + (nt & 1)];
            MMA_BF16(acc[0][nt], ah[0], b0, b1);
            MMA_BF16(acc[1][nt], ah[1], b0, b1);
        }
        #pragma unroll
        for (int nt = 0; nt < 4; nt++) {
            uint32_t b0 = bh[nt >> 1][nt & 1], b1 = bh[nt >> 1][2 + (nt & 1)];
            MMA_BF16(acc[0][nt], al[0], b0, b1);
            MMA_BF16(acc[1][nt], al[1], b0, b1);
        }
    }

    // ---- epilogue ----
    const int g = lane >> 2, tg = lane & 3;
    #pragma unroll
    for (int mt = 0; mt < 2; mt++)
        #pragma unroll
        for (int nt = 0; nt < 4; nt++) {
            int row = m0 + wm + mt * 16 + g;
            int col = n0 + wn + nt * 8 + tg * 2;
            float b0v = 0.f, b1v = 0.f;
            if (bias) { b0v = __ldg(&bias[col]); b1v = __ldg(&bias[col + 1]); }
            float2* d0 = (float2*)&C[(size_t)row * N + col];
            float2* d1 = (float2*)&C[(size_t)(row + 8) * N + col];
            *d0 = make_float2(acc[mt][nt][0] + b0v, acc[mt][nt][1] + b1v);
            *d1 = make_float2(acc[mt][nt][2] + b0v, acc[mt][nt][3] + b1v);
        }
}

// ---------------- local-window attention, smem-tiled ----------------
#define QBLK 64
#define JMAX (QBLK + 2*WIN)   // 78

__global__ void __launch_bounds__(256)
local_attn(const float* __restrict__ qkv, __nv_bfloat16* __restrict__ ohi,
           __nv_bfloat16* __restrict__ olo)
{
    __shared__ float ks[JMAX][DH];
    __shared__ float vs[JMAX][DH];

    const int blk = blockIdx.x;
    const int nblk = NSEQ / QBLK;          // 32
    const int i0 = (blk % nblk) * QBLK;
    const int h  = (blk / nblk) % NH;
    const int b  = blk / (nblk * NH);

    const int tid = threadIdx.x, wid = tid >> 5, lane = tid & 31;
    const int doff = h * DH;
    const size_t rbase = (size_t)b * NSEQ;

    const int jbase = (i0 - WIN > 0) ? i0 - WIN : 0;
    const int jend  = (i0 + QBLK - 1 + WIN < NSEQ - 1) ? i0 + QBLK - 1 + WIN : NSEQ - 1;
    const int jtot  = jend - jbase + 1;

    for (int s = tid; s < jtot * 32; s += 256) {
        const int row = s >> 5, c2 = (s & 31) * 2;
        const size_t g = (rbase + jbase + row) * C3 + doff + c2;
        *(float2*)&ks[row][c2] = *(const float2*)(qkv + g + CH);
        *(float2*)&vs[row][c2] = *(const float2*)(qkv + g + 2 * CH);
    }
    __syncthreads();

    const float scale = 0.125f;
    #pragma unroll
    for (int qq = 0; qq < 8; qq++) {
        const int i = i0 + wid * 8 + qq;
        const float2 q = *(const float2*)(qkv + (rbase + i) * C3 + doff + 2 * lane);
        const int j0 = (i - WIN > 0) ? i - WIN : 0;
        const int j1 = (i + WIN < NSEQ - 1) ? i + WIN : NSEQ - 1;
        const int nj = j1 - j0 + 1;
        const int rb = j0 - jbase;

        float lg[2 * WIN + 1];
        for (int jj = 0; jj < nj; jj++) {
            const float2 k = *(const float2*)&ks[rb + jj][2 * lane];
            float s = q.x * k.x + q.y * k.y;
            #pragma unroll
            for (int o = 16; o; o >>= 1) s += __shfl_xor_sync(0xffffffffu, s, o);
            lg[jj] = s * scale;
        }
        float m = -1e30f;
        for (int jj = 0; jj < nj; jj++) m = fmaxf(m, lg[jj]);
        float den = 0.f;
        float2 acc = make_float2(0.f, 0.f);
        for (int jj = 0; jj < nj; jj++) {
            const float p = __expf(lg[jj] - m);
            den += p;
            const float2 v = *(const float2*)&vs[rb + jj][2 * lane];
            acc.x += p * v.x; acc.y += p * v.y;
        }
        const float inv = 1.f / den;
        const float rx = acc.x * inv, ry = acc.y * inv;
        const __nv_bfloat16 hx = __float2bfloat16(rx), hy = __float2bfloat16(ry);
        const __nv_bfloat16 lx = __float2bfloat16(rx - __bfloat162float(hx));
        const __nv_bfloat16 ly = __float2bfloat16(ry - __bfloat162float(hy));
        const size_t off = (rbase + i) * CH + doff + 2 * lane;
        *(__nv_bfloat162*)(ohi + off) = __nv_bfloat162(hx, hy);
        *(__nv_bfloat162*)(olo + off) = __nv_bfloat162(lx, ly);
    }
}

// ---------------- launch ----------------
extern "C" void kernel_launch(void* const* d_in, const int* in_sizes, int n_in,
                              void* d_out, int out_size)
{
    const float* x      = (const float*)d_in[0];
    const float* w_qkv  = (const float*)d_in[1];
    const float* w_proj = (const float*)d_in[2];
    const float* b_proj = (const float*)d_in[3];
    float* out = (float*)d_out;

    float* qkv;
    __nv_bfloat16 *xhi, *xlo, *qhi, *qlo, *phi, *plo, *ahi, *alo;
    cudaGetSymbolAddress((void**)&qkv, g_qkv);
    cudaGetSymbolAddress((void**)&xhi, g_xhi); cudaGetSymbolAddress((void**)&xlo, g_xlo);
    cudaGetSymbolAddress((void**)&qhi, g_qhi); cudaGetSymbolAddress((void**)&qlo, g_qlo);
    cudaGetSymbolAddress((void**)&phi, g_phi); cudaGetSymbolAddress((void**)&plo, g_plo);
    cudaGetSymbolAddress((void**)&ahi, g_ahi); cudaGetSymbolAddress((void**)&alo, g_alo);

    constexpr int SMEM_BIG   = NSTAGE * (2 * 128 * 64 + 16384);  // 128 KB
    constexpr int SMEM_SMALL = NSTAGE * (2 * 64 * 64 + 16384);   // 96 KB
    cudaFuncSetAttribute((void*)gemm_mma<128, 512, 1>, cudaFuncAttributeMaxDynamicSharedMemorySize, SMEM_BIG);
    cudaFuncSetAttribute((void*)gemm_mma<64, 256, 2>,  cudaFuncAttributeMaxDynamicSharedMemorySize, SMEM_SMALL);

    // 1) splits
    {
        int n4 = MTOT * CH / 4;
        split_bf16<<<(n4 + 255) / 256, 256>>>(x, xhi, xlo, n4);
        n4 = C3 * CH / 4;
        split_bf16<<<(n4 + 255) / 256, 256>>>(w_qkv, qhi, qlo, n4);
        n4 = CH * CH / 4;
        split_bf16<<<(n4 + 255) / 256, 256>>>(w_proj, phi, plo, n4);
    }
    // 2) QKV GEMM: [4096, 2304]
    {
        dim3 grid(C3 / 128, MTOT / 128);   // 18 x 32
        gemm_mma<128, 512, 1><<<grid, 512, SMEM_BIG>>>(xhi, xlo, qhi, qlo, nullptr, qkv, C3);
    }
    // 3) attention -> bf16 hi/lo
    {
        const int blocks = BATCH * NH * (NSEQ / QBLK);  // 768
        local_attn<<<blocks, 256>>>(qkv, ahi, alo);
    }
    // 4) proj GEMM: [4096, 768] + bias
    {
        dim3 grid(CH / 128, MTOT / 64);    // 6 x 64
        gemm_mma<64, 256, 2><<<grid, 256, SMEM_SMALL>>>(ahi, alo, phi, plo, b_proj, out, CH);
    }
}

// round 6
// speedup vs baseline: 1.0837x; 1.0837x over previous
#include <cuda_runtime.h>
#include <cuda_bf16.h>
#include <cstdint>

#define BATCH 2
#define NSEQ  2048
#define CH    768
#define NH    12
#define DH    64
#define WIN   7
#define C3    (3*CH)
#define MTOT  (BATCH*NSEQ)   // 4096
#define KDIM  CH             // 768
#define BK    32
#define NCHUNK (KDIM/BK)     // 24

// ---------------- scratch (allocation-free) ----------------
__device__ float         g_qkv[(size_t)MTOT*C3];
__device__ __nv_bfloat16 g_xhi[(size_t)MTOT*CH], g_xlo[(size_t)MTOT*CH];
__device__ __nv_bfloat16 g_qhi[(size_t)C3*CH],  g_qlo[(size_t)C3*CH];
__device__ __nv_bfloat16 g_phi[(size_t)CH*CH],  g_plo[(size_t)CH*CH];
__device__ __nv_bfloat16 g_ahi[(size_t)MTOT*CH], g_alo[(size_t)MTOT*CH];

// ---------------- helpers ----------------
__device__ __forceinline__ uint32_t smem_u32(const void* p) {
    uint32_t a;
    asm("{ .reg .u64 t; cvta.to.shared.u64 t, %1; cvt.u32.u64 %0, t; }" : "=r"(a) : "l"(p));
    return a;
}
__device__ __forceinline__ void cp16(uint32_t dst, const void* src) {
    asm volatile("cp.async.cg.shared.global [%0], [%1], 16;" :: "r"(dst), "l"(src) : "memory");
}
#define CP_COMMIT() asm volatile("cp.async.commit_group;" ::: "memory")
#define CP_WAIT1()  asm volatile("cp.async.wait_group 1;" ::: "memory")

#define LDSM_X4(r0, r1, r2, r3, addr)                                            \
    asm volatile("ldmatrix.sync.aligned.m8n8.x4.shared.b16 {%0,%1,%2,%3}, [%4];" \
                 : "=r"(r0), "=r"(r1), "=r"(r2), "=r"(r3) : "r"(addr))

#define MMA_BF16(acc, a, b0, b1)                                              \
    asm("mma.sync.aligned.m16n8k16.row.col.f32.bf16.bf16.f32 "                \
        "{%0,%1,%2,%3},{%4,%5,%6,%7},{%8,%9},{%0,%1,%2,%3};"                  \
        : "+f"((acc)[0]), "+f"((acc)[1]), "+f"((acc)[2]), "+f"((acc)[3])      \
        : "r"((a)[0]), "r"((a)[1]), "r"((a)[2]), "r"((a)[3]),                 \
          "r"(b0), "r"(b1))

__device__ __forceinline__ uint32_t swz(int row, int colb) {
    return (uint32_t)(row * 64 + (colb ^ ((row & 6) << 3)));
}

// ---------------- fused fp32 -> bf16 hi/lo splits (3 arrays, 1 launch) ----------------
#define N4_X  (MTOT*CH/4)
#define N4_Q  (C3*CH/4)
#define N4_P  (CH*CH/4)

__device__ __forceinline__ void split4(const float* __restrict__ in,
    __nv_bfloat16* __restrict__ hi, __nv_bfloat16* __restrict__ lo, int idx)
{
    float4 v = ((const float4*)in)[idx];
    __nv_bfloat16 h0 = __float2bfloat16(v.x), h1 = __float2bfloat16(v.y);
    __nv_bfloat16 h2 = __float2bfloat16(v.z), h3 = __float2bfloat16(v.w);
    __nv_bfloat16 l0 = __float2bfloat16(v.x - __bfloat162float(h0));
    __nv_bfloat16 l1 = __float2bfloat16(v.y - __bfloat162float(h1));
    __nv_bfloat16 l2 = __float2bfloat16(v.z - __bfloat162float(h2));
    __nv_bfloat16 l3 = __float2bfloat16(v.w - __bfloat162float(h3));
    __nv_bfloat162* hp = (__nv_bfloat162*)(hi + 4 * (size_t)idx);
    __nv_bfloat162* lp = (__nv_bfloat162*)(lo + 4 * (size_t)idx);
    hp[0] = __nv_bfloat162(h0, h1); hp[1] = __nv_bfloat162(h2, h3);
    lp[0] = __nv_bfloat162(l0, l1); lp[1] = __nv_bfloat162(l2, l3);
}

__global__ void __launch_bounds__(256)
split_all(const float* __restrict__ x, const float* __restrict__ wq,
          const float* __restrict__ wp,
          __nv_bfloat16* __restrict__ xhi, __nv_bfloat16* __restrict__ xlo,
          __nv_bfloat16* __restrict__ qhi, __nv_bfloat16* __restrict__ qlo,
          __nv_bfloat16* __restrict__ phi, __nv_bfloat16* __restrict__ plo)
{
    int idx = blockIdx.x * blockDim.x + threadIdx.x;
    if (idx < N4_X)                 split4(x,  xhi, xlo, idx);
    else if (idx < N4_X + N4_Q)     split4(wq, qhi, qlo, idx - N4_X);
    else if (idx < N4_X + N4_Q + N4_P) split4(wp, phi, plo, idx - N4_X - N4_Q);
}

// ---------------- HMMA GEMM: 3-stage ring, 2 CTAs/SM, 8 warps (2x4) ----------------
// Stage layout: [Ahi BM*64][Alo BM*64][Whi 8192][Wlo 8192]
template<int BM_>
__global__ void __launch_bounds__(256, 2)
gemm_mma(const __nv_bfloat16* __restrict__ Ahi, const __nv_bfloat16* __restrict__ Alo,
         const __nv_bfloat16* __restrict__ Whi, const __nv_bfloat16* __restrict__ Wlo,
         const float* __restrict__ bias, float* __restrict__ C, int N)
{
    constexpr int MT     = BM_ / 32;          // m16 tiles per warp
    constexpr int ATILE  = BM_ * 64;
    constexpr int STAGEB = 2 * ATILE + 16384;

    extern __shared__ char smem[];
    const uint32_t sb = smem_u32(smem);
    const int tid = threadIdx.x, wid = tid >> 5, lane = tid & 31;
    const int m0 = blockIdx.y * BM_, n0 = blockIdx.x * 128;
    const int wm = (wid >> 2) * (BM_ / 2);    // 2 warp rows
    const int wn = (wid & 3) * 32;            // 4 warp cols

    const char* pAh = (const char*)Ahi;
    const char* pAl = (const char*)Alo;
    const char* pWh = (const char*)Whi;
    const char* pWl = (const char*)Wlo;

    float acc[MT][4][4];
    #pragma unroll
    for (int i = 0; i < MT; i++)
        #pragma unroll
        for (int j = 0; j < 4; j++)
            #pragma unroll
            for (int t = 0; t < 4; t++) acc[i][j][t] = 0.f;

    auto fill_stage = [&](uint32_t stb, int k0) {
        #pragma unroll
        for (int s = tid; s < BM_ * 4; s += 256) {
            int row = s >> 2, ks = s & 3;
            uint32_t so = swz(row, ks * 16);
            size_t ga = ((size_t)(m0 + row) * KDIM + k0 + ks * 8) * 2;
            cp16(stb + so,         pAh + ga);
            cp16(stb + ATILE + so, pAl + ga);
        }
        #pragma unroll
        for (int s = tid; s < 512; s += 256) {
            int row = s >> 2, ks = s & 3;
            uint32_t so = swz(row, ks * 16);
            size_t gw = ((size_t)(n0 + row) * KDIM + k0 + ks * 8) * 2;
            cp16(stb + 2 * ATILE + so,        pWh + gw);
            cp16(stb + 2 * ATILE + 8192 + so, pWl + gw);
        }
    };

    // prologue: chunks 0,1 -> stages 0,1
    fill_stage(sb, 0);           CP_COMMIT();
    fill_stage(sb + STAGEB, BK); CP_COMMIT();

    const int r = lane & 15, cg = lane >> 4;
    int scons = 0, sfill = 2;    // consume / fill stage indices

    #pragma unroll 1
    for (int c = 0; c < NCHUNK; c++) {
        const uint32_t stb = sb + scons * STAGEB;

        CP_WAIT1();              // chunk c arrived (committed at iter c-2 / prologue)
        __syncthreads();         // visible to all warps; stage sfill fully drained

        // refill drained stage with chunk c+2 (overlaps with compute below)
        if (c + 2 < NCHUNK)
            fill_stage(sb + sfill * STAGEB, (c + 2) * BK);
        CP_COMMIT();

        #pragma unroll
        for (int kstep = 0; kstep < 2; kstep++) {
            const int kb = kstep * 32;
            uint32_t ah[MT][4], al[MT][4], bh[2][4], bl[2][4];
            #pragma unroll
            for (int mt = 0; mt < MT; mt++) {
                uint32_t ad = stb + swz(wm + mt * 16 + r, kb + cg * 16);
                LDSM_X4(ah[mt][0], ah[mt][1], ah[mt][2], ah[mt][3], ad);
                LDSM_X4(al[mt][0], al[mt][1], al[mt][2], al[mt][3], ad + ATILE);
            }
            #pragma unroll
            for (int bt = 0; bt < 2; bt++) {
                uint32_t ad = stb + 2 * ATILE + swz(wn + bt * 16 + r, kb + cg * 16);
                LDSM_X4(bh[bt][0], bh[bt][1], bh[bt][2], bh[bt][3], ad);
                LDSM_X4(bl[bt][0], bl[bt][1], bl[bt][2], bl[bt][3], ad + 8192);
            }
            // product 1: Ahi x Whi
            #pragma unroll
            for (int nt = 0; nt < 4; nt++) {
                uint32_t b0 = bh[nt >> 1][nt & 1], b1 = bh[nt >> 1][2 + (nt & 1)];
                #pragma unroll
                for (int mt = 0; mt < MT; mt++) MMA_BF16(acc[mt][nt], ah[mt], b0, b1);
            }
            // product 2: Ahi x Wlo
            #pragma unroll
            for (int nt = 0; nt < 4; nt++) {
                uint32_t b0 = bl[nt >> 1][nt & 1], b1 = bl[nt >> 1][2 + (nt & 1)];
                #pragma unroll
                for (int mt = 0; mt < MT; mt++) MMA_BF16(acc[mt][nt], ah[mt], b0, b1);
            }
            // product 3: Alo x Whi
            #pragma unroll
            for (int nt = 0; nt < 4; nt++) {
                uint32_t b0 = bh[nt >> 1][nt & 1], b1 = bh[nt >> 1][2 + (nt & 1)];
                #pragma unroll
                for (int mt = 0; mt < MT; mt++) MMA_BF16(acc[mt][nt], al[mt], b0, b1);
            }
        }

        scons = (scons == 2) ? 0 : scons + 1;
        sfill = (sfill == 2) ? 0 : sfill + 1;
    }

    // ---- epilogue ----
    const int g = lane >> 2, tg = lane & 3;
    #pragma unroll
    for (int mt = 0; mt < MT; mt++)
        #pragma unroll
        for (int nt = 0; nt < 4; nt++) {
            int row = m0 + wm + mt * 16 + g;
            int col = n0 + wn + nt * 8 + tg * 2;
            float b0v = 0.f, b1v = 0.f;
            if (bias) { b0v = __ldg(&bias[col]); b1v = __ldg(&bias[col + 1]); }
            float2* d0 = (float2*)&C[(size_t)row * N + col];
            float2* d1 = (float2*)&C[(size_t)(row + 8) * N + col];
            *d0 = make_float2(acc[mt][nt][0] + b0v, acc[mt][nt][1] + b1v);
            *d1 = make_float2(acc[mt][nt][2] + b0v, acc[mt][nt][3] + b1v);
        }
}

// ---------------- local-window attention, smem-tiled ----------------
#define QBLK 64
#define JMAX (QBLK + 2*WIN)   // 78

__global__ void __launch_bounds__(256)
local_attn(const float* __restrict__ qkv, __nv_bfloat16* __restrict__ ohi,
           __nv_bfloat16* __restrict__ olo)
{
    __shared__ float ks[JMAX][DH];
    __shared__ float vs[JMAX][DH];

    const int blk = blockIdx.x;
    const int nblk = NSEQ / QBLK;          // 32
    const int i0 = (blk % nblk) * QBLK;
    const int h  = (blk / nblk) % NH;
    const int b  = blk / (nblk * NH);

    const int tid = threadIdx.x, wid = tid >> 5, lane = tid & 31;
    const int doff = h * DH;
    const size_t rbase = (size_t)b * NSEQ;

    const int jbase = (i0 - WIN > 0) ? i0 - WIN : 0;
    const int jend  = (i0 + QBLK - 1 + WIN < NSEQ - 1) ? i0 + QBLK - 1 + WIN : NSEQ - 1;
    const int jtot  = jend - jbase + 1;

    for (int s = tid; s < jtot * 32; s += 256) {
        const int row = s >> 5, c2 = (s & 31) * 2;
        const size_t g = (rbase + jbase + row) * C3 + doff + c2;
        *(float2*)&ks[row][c2] = *(const float2*)(qkv + g + CH);
        *(float2*)&vs[row][c2] = *(const float2*)(qkv + g + 2 * CH);
    }
    __syncthreads();

    const float scale = 0.125f;
    #pragma unroll
    for (int qq = 0; qq < 8; qq++) {
        const int i = i0 + wid * 8 + qq;
        const float2 q = *(const float2*)(qkv + (rbase + i) * C3 + doff + 2 * lane);
        const int j0 = (i - WIN > 0) ? i - WIN : 0;
        const int j1 = (i + WIN < NSEQ - 1) ? i + WIN : NSEQ - 1;
        const int nj = j1 - j0 + 1;
        const int rb = j0 - jbase;

        float lg[2 * WIN + 1];
        for (int jj = 0; jj < nj; jj++) {
            const float2 k = *(const float2*)&ks[rb + jj][2 * lane];
            float s = q.x * k.x + q.y * k.y;
            #pragma unroll
            for (int o = 16; o; o >>= 1) s += __shfl_xor_sync(0xffffffffu, s, o);
            lg[jj] = s * scale;
        }
        float m = -1e30f;
        for (int jj = 0; jj < nj; jj++) m = fmaxf(m, lg[jj]);
        float den = 0.f;
        float2 acc = make_float2(0.f, 0.f);
        for (int jj = 0; jj < nj; jj++) {
            const float p = __expf(lg[jj] - m);
            den += p;
            const float2 v = *(const float2*)&vs[rb + jj][2 * lane];
            acc.x += p * v.x; acc.y += p * v.y;
        }
        const float inv = 1.f / den;
        const float rx = acc.x * inv, ry = acc.y * inv;
        const __nv_bfloat16 hx = __float2bfloat16(rx), hy = __float2bfloat16(ry);
        const __nv_bfloat16 lx = __float2bfloat16(rx - __bfloat162float(hx));
        const __nv_bfloat16 ly = __float2bfloat16(ry - __bfloat162float(hy));
        const size_t off = (rbase + i) * CH + doff + 2 * lane;
        *(__nv_bfloat162*)(ohi + off) = __nv_bfloat162(hx, hy);
        *(__nv_bfloat162*)(olo + off) = __nv_bfloat162(lx, ly);
    }
}

// ---------------- launch ----------------
extern "C" void kernel_launch(void* const* d_in, const int* in_sizes, int n_in,
                              void* d_out, int out_size)
{
    const float* x      = (const float*)d_in[0];
    const float* w_qkv  = (const float*)d_in[1];
    const float* w_proj = (const float*)d_in[2];
    const float* b_proj = (const float*)d_in[3];
    float* out = (float*)d_out;

    float* qkv;
    __nv_bfloat16 *xhi, *xlo, *qhi, *qlo, *phi, *plo, *ahi, *alo;
    cudaGetSymbolAddress((void**)&qkv, g_qkv);
    cudaGetSymbolAddress((void**)&xhi, g_xhi); cudaGetSymbolAddress((void**)&xlo, g_xlo);
    cudaGetSymbolAddress((void**)&qhi, g_qhi); cudaGetSymbolAddress((void**)&qlo, g_qlo);
    cudaGetSymbolAddress((void**)&phi, g_phi); cudaGetSymbolAddress((void**)&plo, g_plo);
    cudaGetSymbolAddress((void**)&ahi, g_ahi); cudaGetSymbolAddress((void**)&alo, g_alo);

    constexpr int SMEM_BIG   = 3 * (2 * 128 * 64 + 16384);  // 96 KB
    constexpr int SMEM_SMALL = 3 * (2 * 64 * 64 + 16384);   // 72 KB
    cudaFuncSetAttribute((void*)gemm_mma<128>, cudaFuncAttributeMaxDynamicSharedMemorySize, SMEM_BIG);
    cudaFuncSetAttribute((void*)gemm_mma<64>,  cudaFuncAttributeMaxDynamicSharedMemorySize, SMEM_SMALL);

    // 1) fused splits (one launch)
    {
        const int n4 = N4_X + N4_Q + N4_P;
        split_all<<<(n4 + 255) / 256, 256>>>(x, w_qkv, w_proj,
                                             xhi, xlo, qhi, qlo, phi, plo);
    }
    // 2) QKV GEMM: [4096, 2304]
    {
        dim3 grid(C3 / 128, MTOT / 128);   // 18 x 32
        gemm_mma<128><<<grid, 256, SMEM_BIG>>>(xhi, xlo, qhi, qlo, nullptr, qkv, C3);
    }
    // 3) attention -> bf16 hi/lo
    {
        const int blocks = BATCH * NH * (NSEQ / QBLK);  // 768
        local_attn<<<blocks, 256>>>(qkv, ahi, alo);
    }
    // 4) proj GEMM: [4096, 768] + bias
    {
        dim3 grid(CH / 128, MTOT / 64);    // 6 x 64
        gemm_mma<64><<<grid, 256, SMEM_SMALL>>>(ahi, alo, phi, plo, b_proj, out, CH);
    }
}

// round 7
// speedup vs baseline: 1.4219x; 1.3121x over previous
#include <cuda_runtime.h>
#include <cuda_fp16.h>
#include <cstdint>

#define BATCH 2
#define NSEQ  2048
#define CH    768
#define NH    12
#define DH    64
#define WIN   7
#define C3    (3*CH)
#define MTOT  (BATCH*NSEQ)   // 4096
#define KDIM  CH             // 768
#define BK    32
#define NCHUNK (KDIM/BK)     // 24

// ---------------- scratch (allocation-free) ----------------
__device__ float g_qkv[(size_t)MTOT*C3];
__device__ __half g_x16[(size_t)MTOT*CH];
__device__ __half g_qhi[(size_t)C3*CH],  g_qlo[(size_t)C3*CH];
__device__ __half g_phi[(size_t)CH*CH],  g_plo[(size_t)CH*CH];
__device__ __half g_att[(size_t)MTOT*CH];

// ---------------- helpers ----------------
__device__ __forceinline__ uint32_t smem_u32(const void* p) {
    uint32_t a;
    asm("{ .reg .u64 t; cvta.to.shared.u64 t, %1; cvt.u32.u64 %0, t; }" : "=r"(a) : "l"(p));
    return a;
}
__device__ __forceinline__ void cp16(uint32_t dst, const void* src) {
    asm volatile("cp.async.cg.shared.global [%0], [%1], 16;" :: "r"(dst), "l"(src) : "memory");
}
#define CP_COMMIT() asm volatile("cp.async.commit_group;" ::: "memory")
#define CP_WAIT1()  asm volatile("cp.async.wait_group 1;" ::: "memory")

#define LDSM_X4(r0, r1, r2, r3, addr)                                            \
    asm volatile("ldmatrix.sync.aligned.m8n8.x4.shared.b16 {%0,%1,%2,%3}, [%4];" \
                 : "=r"(r0), "=r"(r1), "=r"(r2), "=r"(r3) : "r"(addr))

#define MMA_F16(acc, a, b0, b1)                                               \
    asm("mma.sync.aligned.m16n8k16.row.col.f32.f16.f16.f32 "                  \
        "{%0,%1,%2,%3},{%4,%5,%6,%7},{%8,%9},{%0,%1,%2,%3};"                  \
        : "+f"((acc)[0]), "+f"((acc)[1]), "+f"((acc)[2]), "+f"((acc)[3])      \
        : "r"((a)[0]), "r"((a)[1]), "r"((a)[2]), "r"((a)[3]),                 \
          "r"(b0), "r"(b1))

__device__ __forceinline__ uint32_t swz(int row, int colb) {
    return (uint32_t)(row * 64 + (colb ^ ((row & 6) << 3)));
}

// ---------------- fused conversions: x -> fp16; w_qkv, w_proj -> fp16 hi/lo ----------------
#define N4_X  (MTOT*CH/4)
#define N4_Q  (C3*CH/4)
#define N4_P  (CH*CH/4)

__device__ __forceinline__ void conv4(const float* __restrict__ in,
                                      __half* __restrict__ o, int idx)
{
    float4 v = ((const float4*)in)[idx];
    __half2* op = (__half2*)(o + 4 * (size_t)idx);
    op[0] = __floats2half2_rn(v.x, v.y);
    op[1] = __floats2half2_rn(v.z, v.w);
}
__device__ __forceinline__ void split4(const float* __restrict__ in,
    __half* __restrict__ hi, __half* __restrict__ lo, int idx)
{
    float4 v = ((const float4*)in)[idx];
    __half h0 = __float2half(v.x), h1 = __float2half(v.y);
    __half h2 = __float2half(v.z), h3 = __float2half(v.w);
    __half l0 = __float2half(v.x - __half2float(h0));
    __half l1 = __float2half(v.y - __half2float(h1));
    __half l2 = __float2half(v.z - __half2float(h2));
    __half l3 = __float2half(v.w - __half2float(h3));
    __half2* hp = (__half2*)(hi + 4 * (size_t)idx);
    __half2* lp = (__half2*)(lo + 4 * (size_t)idx);
    hp[0] = __half2(h0, h1); hp[1] = __half2(h2, h3);
    lp[0] = __half2(l0, l1); lp[1] = __half2(l2, l3);
}

__global__ void __launch_bounds__(256)
split_all(const float* __restrict__ x, const float* __restrict__ wq,
          const float* __restrict__ wp,
          __half* __restrict__ x16,
          __half* __restrict__ qhi, __half* __restrict__ qlo,
          __half* __restrict__ phi, __half* __restrict__ plo)
{
    int idx = blockIdx.x * blockDim.x + threadIdx.x;
    if (idx < N4_X)                    conv4(x, x16, idx);
    else if (idx < N4_X + N4_Q)        split4(wq, qhi, qlo, idx - N4_X);
    else if (idx < N4_X + N4_Q + N4_P) split4(wp, phi, plo, idx - N4_X - N4_Q);
}

// ---------------- HMMA GEMM: A16 @ (Whi+Wlo)^T, 2 products, 3-stage ring ----------------
// Stage layout: [A BM*64][Whi 8192][Wlo 8192]
template<int BM_, int MINCTA>
__global__ void __launch_bounds__(256, MINCTA)
gemm2(const __half* __restrict__ A, const __half* __restrict__ Whi,
      const __half* __restrict__ Wlo,
      const float* __restrict__ bias, float* __restrict__ C, int N)
{
    constexpr int MT     = BM_ / 32;
    constexpr int ATILE  = BM_ * 64;
    constexpr int STAGEB = ATILE + 16384;

    extern __shared__ char smem[];
    const uint32_t sb = smem_u32(smem);
    const int tid = threadIdx.x, wid = tid >> 5, lane = tid & 31;
    const int m0 = blockIdx.y * BM_, n0 = blockIdx.x * 128;
    const int wm = (wid >> 2) * (BM_ / 2);    // 2 warp rows
    const int wn = (wid & 3) * 32;            // 4 warp cols

    const char* pA  = (const char*)A;
    const char* pWh = (const char*)Whi;
    const char* pWl = (const char*)Wlo;

    float acc[MT][4][4];
    #pragma unroll
    for (int i = 0; i < MT; i++)
        #pragma unroll
        for (int j = 0; j < 4; j++)
            #pragma unroll
            for (int t = 0; t < 4; t++) acc[i][j][t] = 0.f;

    auto fill_stage = [&](uint32_t stb, int k0) {
        #pragma unroll
        for (int s = tid; s < BM_ * 4; s += 256) {
            int row = s >> 2, ks = s & 3;
            uint32_t so = swz(row, ks * 16);
            size_t ga = ((size_t)(m0 + row) * KDIM + k0 + ks * 8) * 2;
            cp16(stb + so, pA + ga);
        }
        #pragma unroll
        for (int s = tid; s < 512; s += 256) {
            int row = s >> 2, ks = s & 3;
            uint32_t so = swz(row, ks * 16);
            size_t gw = ((size_t)(n0 + row) * KDIM + k0 + ks * 8) * 2;
            cp16(stb + ATILE + so,        pWh + gw);
            cp16(stb + ATILE + 8192 + so, pWl + gw);
        }
    };

    // prologue: chunks 0,1 -> stages 0,1
    fill_stage(sb, 0);           CP_COMMIT();
    fill_stage(sb + STAGEB, BK); CP_COMMIT();

    const int r = lane & 15, cg = lane >> 4;
    int scons = 0, sfill = 2;

    #pragma unroll 1
    for (int c = 0; c < NCHUNK; c++) {
        const uint32_t stb = sb + scons * STAGEB;

        CP_WAIT1();
        __syncthreads();

        if (c + 2 < NCHUNK)
            fill_stage(sb + sfill * STAGEB, (c + 2) * BK);
        CP_COMMIT();

        #pragma unroll
        for (int kstep = 0; kstep < 2; kstep++) {
            const int kb = kstep * 32;
            uint32_t av[MT][4], bh[2][4], bl[2][4];
            #pragma unroll
            for (int mt = 0; mt < MT; mt++) {
                uint32_t ad = stb + swz(wm + mt * 16 + r, kb + cg * 16);
                LDSM_X4(av[mt][0], av[mt][1], av[mt][2], av[mt][3], ad);
            }
            #pragma unroll
            for (int bt = 0; bt < 2; bt++) {
                uint32_t ad = stb + ATILE + swz(wn + bt * 16 + r, kb + cg * 16);
                LDSM_X4(bh[bt][0], bh[bt][1], bh[bt][2], bh[bt][3], ad);
                LDSM_X4(bl[bt][0], bl[bt][1], bl[bt][2], bl[bt][3], ad + 8192);
            }
            // product 1: A x Whi
            #pragma unroll
            for (int nt = 0; nt < 4; nt++) {
                uint32_t b0 = bh[nt >> 1][nt & 1], b1 = bh[nt >> 1][2 + (nt & 1)];
                #pragma unroll
                for (int mt = 0; mt < MT; mt++) MMA_F16(acc[mt][nt], av[mt], b0, b1);
            }
            // product 2: A x Wlo
            #pragma unroll
            for (int nt = 0; nt < 4; nt++) {
                uint32_t b0 = bl[nt >> 1][nt & 1], b1 = bl[nt >> 1][2 + (nt & 1)];
                #pragma unroll
                for (int mt = 0; mt < MT; mt++) MMA_F16(acc[mt][nt], av[mt], b0, b1);
            }
        }

        scons = (scons == 2) ? 0 : scons + 1;
        sfill = (sfill == 2) ? 0 : sfill + 1;
    }

    // ---- epilogue ----
    const int g = lane >> 2, tg = lane & 3;
    #pragma unroll
    for (int mt = 0; mt < MT; mt++)
        #pragma unroll
        for (int nt = 0; nt < 4; nt++) {
            int row = m0 + wm + mt * 16 + g;
            int col = n0 + wn + nt * 8 + tg * 2;
            float b0v = 0.f, b1v = 0.f;
            if (bias) { b0v = __ldg(&bias[col]); b1v = __ldg(&bias[col + 1]); }
            float2* d0 = (float2*)&C[(size_t)row * N + col];
            float2* d1 = (float2*)&C[(size_t)(row + 8) * N + col];
            *d0 = make_float2(acc[mt][nt][0] + b0v, acc[mt][nt][1] + b1v);
            *d1 = make_float2(acc[mt][nt][2] + b0v, acc[mt][nt][3] + b1v);
        }
}

// ---------------- local-window attention, smem-tiled; fp16 output ----------------
#define QBLK 64
#define JMAX (QBLK + 2*WIN)   // 78

__global__ void __launch_bounds__(256)
local_attn(const float* __restrict__ qkv, __half* __restrict__ oatt)
{
    __shared__ float ks[JMAX][DH];
    __shared__ float vs[JMAX][DH];

    const int blk = blockIdx.x;
    const int nblk = NSEQ / QBLK;          // 32
    const int i0 = (blk % nblk) * QBLK;
    const int h  = (blk / nblk) % NH;
    const int b  = blk / (nblk * NH);

    const int tid = threadIdx.x, wid = tid >> 5, lane = tid & 31;
    const int doff = h * DH;
    const size_t rbase = (size_t)b * NSEQ;

    const int jbase = (i0 - WIN > 0) ? i0 - WIN : 0;
    const int jend  = (i0 + QBLK - 1 + WIN < NSEQ - 1) ? i0 + QBLK - 1 + WIN : NSEQ - 1;
    const int jtot  = jend - jbase + 1;

    for (int s = tid; s < jtot * 32; s += 256) {
        const int row = s >> 5, c2 = (s & 31) * 2;
        const size_t g = (rbase + jbase + row) * C3 + doff + c2;
        *(float2*)&ks[row][c2] = *(const float2*)(qkv + g + CH);
        *(float2*)&vs[row][c2] = *(const float2*)(qkv + g + 2 * CH);
    }
    __syncthreads();

    const float scale = 0.125f;
    #pragma unroll
    for (int qq = 0; qq < 8; qq++) {
        const int i = i0 + wid * 8 + qq;
        const float2 q = *(const float2*)(qkv + (rbase + i) * C3 + doff + 2 * lane);
        const int j0 = (i - WIN > 0) ? i - WIN : 0;
        const int j1 = (i + WIN < NSEQ - 1) ? i + WIN : NSEQ - 1;
        const int nj = j1 - j0 + 1;
        const int rb = j0 - jbase;

        float lg[2 * WIN + 1];
        for (int jj = 0; jj < nj; jj++) {
            const float2 k = *(const float2*)&ks[rb + jj][2 * lane];
            float s = q.x * k.x + q.y * k.y;
            #pragma unroll
            for (int o = 16; o; o >>= 1) s += __shfl_xor_sync(0xffffffffu, s, o);
            lg[jj] = s * scale;
        }
        float m = -1e30f;
        for (int jj = 0; jj < nj; jj++) m = fmaxf(m, lg[jj]);
        float den = 0.f;
        float2 acc = make_float2(0.f, 0.f);
        for (int jj = 0; jj < nj; jj++) {
            const float p = __expf(lg[jj] - m);
            den += p;
            const float2 v = *(const float2*)&vs[rb + jj][2 * lane];
            acc.x += p * v.x; acc.y += p * v.y;
        }
        const float inv = 1.f / den;
        const size_t off = (rbase + i) * CH + doff + 2 * lane;
        *(__half2*)(oatt + off) = __floats2half2_rn(acc.x * inv, acc.y * inv);
    }
}

// ---------------- launch ----------------
extern "C" void kernel_launch(void* const* d_in, const int* in_sizes, int n_in,
                              void* d_out, int out_size)
{
    const float* x      = (const float*)d_in[0];
    const float* w_qkv  = (const float*)d_in[1];
    const float* w_proj = (const float*)d_in[2];
    const float* b_proj = (const float*)d_in[3];
    float* out = (float*)d_out;

    float* qkv;
    __half *x16, *qhi, *qlo, *phi, *plo, *att;
    cudaGetSymbolAddress((void**)&qkv, g_qkv);
    cudaGetSymbolAddress((void**)&x16, g_x16);
    cudaGetSymbolAddress((void**)&qhi, g_qhi); cudaGetSymbolAddress((void**)&qlo, g_qlo);
    cudaGetSymbolAddress((void**)&phi, g_phi); cudaGetSymbolAddress((void**)&plo, g_plo);
    cudaGetSymbolAddress((void**)&att, g_att);

    constexpr int SMEM_BIG   = 3 * (128 * 64 + 16384);  // 72 KB (BM=128)
    constexpr int SMEM_SMALL = 3 * (64 * 64 + 16384);   // 60 KB (BM=64)
    cudaFuncSetAttribute((void*)gemm2<128, 2>, cudaFuncAttributeMaxDynamicSharedMemorySize, SMEM_BIG);
    cudaFuncSetAttribute((void*)gemm2<64, 3>,  cudaFuncAttributeMaxDynamicSharedMemorySize, SMEM_SMALL);

    // 1) fused conversions
    {
        const int n4 = N4_X + N4_Q + N4_P;
        split_all<<<(n4 + 255) / 256, 256>>>(x, w_qkv, w_proj,
                                             x16, qhi, qlo, phi, plo);
    }
    // 2) QKV GEMM: [4096, 2304] = x16 @ (w_qkv hi+lo)^T
    {
        dim3 grid(C3 / 128, MTOT / 128);   // 18 x 32 = 576
        gemm2<128, 2><<<grid, 256, SMEM_BIG>>>(x16, qhi, qlo, nullptr, qkv, C3);
    }
    // 3) attention -> fp16
    {
        const int blocks = BATCH * NH * (NSEQ / QBLK);  // 768
        local_attn<<<blocks, 256>>>(qkv, att);
    }
    // 4) proj GEMM: [4096, 768] + bias (one wave at 3 CTAs/SM)
    {
        dim3 grid(CH / 128, MTOT / 64);    // 6 x 64 = 384
        gemm2<64, 3><<<grid, 256, SMEM_SMALL>>>(att, phi, plo, b_proj, out, CH);
    }
}

// round 8
// speedup vs baseline: 1.4839x; 1.0436x over previous
#include <cuda_runtime.h>
#include <cuda_fp16.h>
#include <cstdint>

#define BATCH 2
#define NSEQ  2048
#define CH    768
#define NH    12
#define DH    64
#define WIN   7
#define C3    (3*CH)
#define MTOT  (BATCH*NSEQ)   // 4096
#define KDIM  CH             // 768
#define BK    64
#define NCHUNK (KDIM/BK)     // 12

// ---------------- scratch (allocation-free) ----------------
__device__ float g_qkv[(size_t)MTOT*C3];
__device__ __half g_x16[(size_t)MTOT*CH];
__device__ __half g_qhi[(size_t)C3*CH],  g_qlo[(size_t)C3*CH];
__device__ __half g_phi[(size_t)CH*CH],  g_plo[(size_t)CH*CH];
__device__ __half g_att[(size_t)MTOT*CH];

// ---------------- helpers ----------------
__device__ __forceinline__ uint32_t smem_u32(const void* p) {
    uint32_t a;
    asm("{ .reg .u64 t; cvta.to.shared.u64 t, %1; cvt.u32.u64 %0, t; }" : "=r"(a) : "l"(p));
    return a;
}
__device__ __forceinline__ void cp16(uint32_t dst, const void* src) {
    asm volatile("cp.async.cg.shared.global [%0], [%1], 16;" :: "r"(dst), "l"(src) : "memory");
}
#define CP_COMMIT() asm volatile("cp.async.commit_group;" ::: "memory")
#define CP_WAIT0()  asm volatile("cp.async.wait_group 0;" ::: "memory")

#define LDSM_X4(r0, r1, r2, r3, addr)                                            \
    asm volatile("ldmatrix.sync.aligned.m8n8.x4.shared.b16 {%0,%1,%2,%3}, [%4];" \
                 : "=r"(r0), "=r"(r1), "=r"(r2), "=r"(r3) : "r"(addr))

#define MMA_F16(acc, a, b0, b1)                                               \
    asm("mma.sync.aligned.m16n8k16.row.col.f32.f16.f16.f32 "                  \
        "{%0,%1,%2,%3},{%4,%5,%6,%7},{%8,%9},{%0,%1,%2,%3};"                  \
        : "+f"((acc)[0]), "+f"((acc)[1]), "+f"((acc)[2]), "+f"((acc)[3])      \
        : "r"((a)[0]), "r"((a)[1]), "r"((a)[2]), "r"((a)[3]),                 \
          "r"(b0), "r"(b1))

// swizzled offset within a rows x 128B tile: full 8-position 16B permutation
__device__ __forceinline__ uint32_t swz(int row, int colb) {
    return (uint32_t)(row * 128 + (colb ^ ((row & 7) << 4)));
}

// ---------------- fused conversions ----------------
#define N4_X  (MTOT*CH/4)
#define N4_Q  (C3*CH/4)
#define N4_P  (CH*CH/4)

__device__ __forceinline__ void conv4(const float* __restrict__ in,
                                      __half* __restrict__ o, int idx)
{
    float4 v = ((const float4*)in)[idx];
    __half2* op = (__half2*)(o + 4 * (size_t)idx);
    op[0] = __floats2half2_rn(v.x, v.y);
    op[1] = __floats2half2_rn(v.z, v.w);
}
__device__ __forceinline__ void split4(const float* __restrict__ in,
    __half* __restrict__ hi, __half* __restrict__ lo, int idx)
{
    float4 v = ((const float4*)in)[idx];
    __half h0 = __float2half(v.x), h1 = __float2half(v.y);
    __half h2 = __float2half(v.z), h3 = __float2half(v.w);
    __half l0 = __float2half(v.x - __half2float(h0));
    __half l1 = __float2half(v.y - __half2float(h1));
    __half l2 = __float2half(v.z - __half2float(h2));
    __half l3 = __float2half(v.w - __half2float(h3));
    __half2* hp = (__half2*)(hi + 4 * (size_t)idx);
    __half2* lp = (__half2*)(lo + 4 * (size_t)idx);
    hp[0] = __half2(h0, h1); hp[1] = __half2(h2, h3);
    lp[0] = __half2(l0, l1); lp[1] = __half2(l2, l3);
}

__global__ void __launch_bounds__(256)
split_all(const float* __restrict__ x, const float* __restrict__ wq,
          const float* __restrict__ wp,
          __half* __restrict__ x16,
          __half* __restrict__ qhi, __half* __restrict__ qlo,
          __half* __restrict__ phi, __half* __restrict__ plo)
{
    int idx = blockIdx.x * blockDim.x + threadIdx.x;
    if (idx < N4_X)                    conv4(x, x16, idx);
    else if (idx < N4_X + N4_Q)        split4(wq, qhi, qlo, idx - N4_X);
    else if (idx < N4_X + N4_Q + N4_P) split4(wp, phi, plo, idx - N4_X - N4_Q);
}

// ---------------- HMMA GEMM: BK=64, 2-stage double buffer ----------------
// Stage layout: [A BM*128][Whi BN*128][Wlo BN*128]
template<int BM_, int BN_>
__global__ void __launch_bounds__(256, 2)
gemm2(const __half* __restrict__ A, const __half* __restrict__ Whi,
      const __half* __restrict__ Wlo,
      const float* __restrict__ bias, float* __restrict__ C, int N)
{
    constexpr int MT     = BM_ / 32;       // m16 tiles per warp
    constexpr int NTT    = BN_ / 32;       // n8 tiles per warp
    constexpr int BT     = BN_ / 64;       // 16-row B LDSM groups per warp
    constexpr int ATILE  = BM_ * 128;
    constexpr int WTILE  = BN_ * 128;
    constexpr int STAGEB = ATILE + 2 * WTILE;

    extern __shared__ char smem[];
    const uint32_t sb = smem_u32(smem);
    const int tid = threadIdx.x, wid = tid >> 5, lane = tid & 31;
    const int m0 = blockIdx.y * BM_, n0 = blockIdx.x * BN_;
    const int wm = (wid >> 2) * (BM_ / 2);     // 2 warp rows
    const int wn = (wid & 3) * (BN_ / 4);      // 4 warp cols

    const char* pA  = (const char*)A;
    const char* pWh = (const char*)Whi;
    const char* pWl = (const char*)Wlo;

    float acc[MT][NTT][4];
    #pragma unroll
    for (int i = 0; i < MT; i++)
        #pragma unroll
        for (int j = 0; j < NTT; j++)
            #pragma unroll
            for (int t = 0; t < 4; t++) acc[i][j][t] = 0.f;

    auto fill_stage = [&](uint32_t stb, int k0) {
        #pragma unroll
        for (int s = tid; s < BM_ * 8; s += 256) {
            int row = s >> 3, ks = s & 7;      // 8 x 16B segments per 128B row
            uint32_t so = swz(row, ks * 16);
            size_t ga = ((size_t)(m0 + row) * KDIM + k0 + ks * 8) * 2;
            cp16(stb + so, pA + ga);
        }
        #pragma unroll
        for (int s = tid; s < BN_ * 8; s += 256) {
            int row = s >> 3, ks = s & 7;
            uint32_t so = swz(row, ks * 16);
            size_t gw = ((size_t)(n0 + row) * KDIM + k0 + ks * 8) * 2;
            cp16(stb + ATILE + so,         pWh + gw);
            cp16(stb + ATILE + WTILE + so, pWl + gw);
        }
    };

    // prologue: chunk 0 -> stage 0
    fill_stage(sb, 0);
    CP_COMMIT();

    const int r = lane & 15, cg = lane >> 4;

    #pragma unroll 1
    for (int c = 0; c < NCHUNK; c++) {
        const uint32_t stb = sb + (c & 1) * STAGEB;

        CP_WAIT0();              // chunk c resident
        __syncthreads();         // all warps done with stage (c+1)&1, data visible

        if (c + 1 < NCHUNK)
            fill_stage(sb + ((c + 1) & 1) * STAGEB, (c + 1) * BK);
        CP_COMMIT();

        #pragma unroll
        for (int kstep = 0; kstep < 4; kstep++) {
            const int kb = kstep * 32;          // byte offset: 16 k-elements
            uint32_t av[MT][4], bh[BT][4], bl[BT][4];
            #pragma unroll
            for (int mt = 0; mt < MT; mt++) {
                uint32_t ad = stb + swz(wm + mt * 16 + r, kb + cg * 16);
                LDSM_X4(av[mt][0], av[mt][1], av[mt][2], av[mt][3], ad);
            }
            #pragma unroll
            for (int bt = 0; bt < BT; bt++) {
                uint32_t ad = stb + ATILE + swz(wn + bt * 16 + r, kb + cg * 16);
                LDSM_X4(bh[bt][0], bh[bt][1], bh[bt][2], bh[bt][3], ad);
                LDSM_X4(bl[bt][0], bl[bt][1], bl[bt][2], bl[bt][3], ad + WTILE);
            }
            // product 1: A x Whi
            #pragma unroll
            for (int nt = 0; nt < NTT; nt++) {
                uint32_t b0 = bh[nt >> 1][nt & 1], b1 = bh[nt >> 1][2 + (nt & 1)];
                #pragma unroll
                for (int mt = 0; mt < MT; mt++) MMA_F16(acc[mt][nt], av[mt], b0, b1);
            }
            // product 2: A x Wlo
            #pragma unroll
            for (int nt = 0; nt < NTT; nt++) {
                uint32_t b0 = bl[nt >> 1][nt & 1], b1 = bl[nt >> 1][2 + (nt & 1)];
                #pragma unroll
                for (int mt = 0; mt < MT; mt++) MMA_F16(acc[mt][nt], av[mt], b0, b1);
            }
        }
    }

    // ---- epilogue ----
    const int g = lane >> 2, tg = lane & 3;
    #pragma unroll
    for (int mt = 0; mt < MT; mt++)
        #pragma unroll
        for (int nt = 0; nt < NTT; nt++) {
            int row = m0 + wm + mt * 16 + g;
            int col = n0 + wn + nt * 8 + tg * 2;
            float b0v = 0.f, b1v = 0.f;
            if (bias) { b0v = __ldg(&bias[col]); b1v = __ldg(&bias[col + 1]); }
            float2* d0 = (float2*)&C[(size_t)row * N + col];
            float2* d1 = (float2*)&C[(size_t)(row + 8) * N + col];
            *d0 = make_float2(acc[mt][nt][0] + b0v, acc[mt][nt][1] + b1v);
            *d1 = make_float2(acc[mt][nt][2] + b0v, acc[mt][nt][3] + b1v);
        }
}

// ---------------- local-window attention, smem-tiled; fp16 output ----------------
#define QBLK 64
#define JMAX (QBLK + 2*WIN)   // 78

__global__ void __launch_bounds__(256)
local_attn(const float* __restrict__ qkv, __half* __restrict__ oatt)
{
    __shared__ float ks[JMAX][DH];
    __shared__ float vs[JMAX][DH];

    const int blk = blockIdx.x;
    const int nblk = NSEQ / QBLK;          // 32
    const int i0 = (blk % nblk) * QBLK;
    const int h  = (blk / nblk) % NH;
    const int b  = blk / (nblk * NH);

    const int tid = threadIdx.x, wid = tid >> 5, lane = tid & 31;
    const int doff = h * DH;
    const size_t rbase = (size_t)b * NSEQ;

    const int jbase = (i0 - WIN > 0) ? i0 - WIN : 0;
    const int jend  = (i0 + QBLK - 1 + WIN < NSEQ - 1) ? i0 + QBLK - 1 + WIN : NSEQ - 1;
    const int jtot  = jend - jbase + 1;

    for (int s = tid; s < jtot * 32; s += 256) {
        const int row = s >> 5, c2 = (s & 31) * 2;
        const size_t g = (rbase + jbase + row) * C3 + doff + c2;
        *(float2*)&ks[row][c2] = *(const float2*)(qkv + g + CH);
        *(float2*)&vs[row][c2] = *(const float2*)(qkv + g + 2 * CH);
    }
    __syncthreads();

    const float scale = 0.125f;
    #pragma unroll
    for (int qq = 0; qq < 8; qq++) {
        const int i = i0 + wid * 8 + qq;
        const float2 q = *(const float2*)(qkv + (rbase + i) * C3 + doff + 2 * lane);
        const int j0 = (i - WIN > 0) ? i - WIN : 0;
        const int j1 = (i + WIN < NSEQ - 1) ? i + WIN : NSEQ - 1;
        const int nj = j1 - j0 + 1;
        const int rb = j0 - jbase;

        float lg[2 * WIN + 1];
        for (int jj = 0; jj < nj; jj++) {
            const float2 k = *(const float2*)&ks[rb + jj][2 * lane];
            float s = q.x * k.x + q.y * k.y;
            #pragma unroll
            for (int o = 16; o; o >>= 1) s += __shfl_xor_sync(0xffffffffu, s, o);
            lg[jj] = s * scale;
        }
        float m = -1e30f;
        for (int jj = 0; jj < nj; jj++) m = fmaxf(m, lg[jj]);
        float den = 0.f;
        float2 acc = make_float2(0.f, 0.f);
        for (int jj = 0; jj < nj; jj++) {
            const float p = __expf(lg[jj] - m);
            den += p;
            const float2 v = *(const float2*)&vs[rb + jj][2 * lane];
            acc.x += p * v.x; acc.y += p * v.y;
        }
        const float inv = 1.f / den;
        const size_t off = (rbase + i) * CH + doff + 2 * lane;
        *(__half2*)(oatt + off) = __floats2half2_rn(acc.x * inv, acc.y * inv);
    }
}

// ---------------- launch ----------------
extern "C" void kernel_launch(void* const* d_in, const int* in_sizes, int n_in,
                              void* d_out, int out_size)
{
    const float* x      = (const float*)d_in[0];
    const float* w_qkv  = (const float*)d_in[1];
    const float* w_proj = (const float*)d_in[2];
    const float* b_proj = (const float*)d_in[3];
    float* out = (float*)d_out;

    float* qkv;
    __half *x16, *qhi, *qlo, *phi, *plo, *att;
    cudaGetSymbolAddress((void**)&qkv, g_qkv);
    cudaGetSymbolAddress((void**)&x16, g_x16);
    cudaGetSymbolAddress((void**)&qhi, g_qhi); cudaGetSymbolAddress((void**)&qlo, g_qlo);
    cudaGetSymbolAddress((void**)&phi, g_phi); cudaGetSymbolAddress((void**)&plo, g_plo);
    cudaGetSymbolAddress((void**)&att, g_att);

    // QKV: BM=128, BN=128 -> stage 48KB, 2 stages = 96KB/CTA, 2 CTAs/SM
    constexpr int SMEM_QKV  = 2 * (128 * 128 + 2 * 128 * 128);   // 98304
    // Proj: BM=64, BN=192 -> stage 56KB, 2 stages = 112KB/CTA, 2 CTAs/SM (224KB)
    constexpr int SMEM_PROJ = 2 * (64 * 128 + 2 * 192 * 128);    // 114688
    cudaFuncSetAttribute((void*)gemm2<128, 128>, cudaFuncAttributeMaxDynamicSharedMemorySize, SMEM_QKV);
    cudaFuncSetAttribute((void*)gemm2<64, 192>,  cudaFuncAttributeMaxDynamicSharedMemorySize, SMEM_PROJ);

    // 1) fused conversions
    {
        const int n4 = N4_X + N4_Q + N4_P;
        split_all<<<(n4 + 255) / 256, 256>>>(x, w_qkv, w_proj,
                                             x16, qhi, qlo, phi, plo);
    }
    // 2) QKV GEMM: [4096, 2304] = x16 @ (w_qkv hi+lo)^T
    {
        dim3 grid(C3 / 128, MTOT / 128);   // 18 x 32 = 576
        gemm2<128, 128><<<grid, 256, SMEM_QKV>>>(x16, qhi, qlo, nullptr, qkv, C3);
    }
    // 3) attention -> fp16
    {
        const int blocks = BATCH * NH * (NSEQ / QBLK);  // 768
        local_attn<<<blocks, 256>>>(qkv, att);
    }
    // 4) proj GEMM: [4096, 768] + bias — one wave (256 CTAs <= 296 slots)
    {
        dim3 grid(CH / 192, MTOT / 64);    // 4 x 64 = 256
        gemm2<64, 192><<<grid, 256, SMEM_PROJ>>>(att, phi, plo, b_proj, out, CH);
    }
}